// round 1
// baseline (speedup 1.0000x reference)
#include <cuda_runtime.h>

// FeatureShader: softmax blend + barycentric vertex-feature sampling.
// Shapes: N=4, H=256, W=256, K=8, C=16; V=100000, F=200000.
// Inputs (metadata order):
//   d_in[0] dists          (N,H,W,K)   float32
//   d_in[1] zbuf           (N,H,W,K)   float32
//   d_in[2] bary_coords    (N,H,W,K,3) float32
//   d_in[3] verts_features (V,C)       float32
//   d_in[4] background     (C,)        float32
//   d_in[5] pix_to_face    (N,H,W,K)   int32
//   d_in[6] faces          (F,3)       int32
// Output: pixel_colors (N,H,W,C) float32

#define NPIX  (4 * 256 * 256)
#define KF    8

__global__ __launch_bounds__(256)
void feature_shader_kernel(const float*  __restrict__ dists,
                           const float*  __restrict__ zbuf,
                           const float*  __restrict__ bary,
                           const float4* __restrict__ vfeat,   // (V, 4 x float4)
                           const float4* __restrict__ bg4,     // (4 x float4)
                           const int*    __restrict__ p2f,
                           const int*    __restrict__ faces,
                           float4*       __restrict__ out4)    // (NPIX, 4 x float4)
{
    int gid = blockIdx.x * blockDim.x + threadIdx.x;
    if (gid >= NPIX * 4) return;
    int pix = gid >> 2;       // pixel id
    int cg  = gid & 3;        // channel group (4 channels each)

    const float INV_SIGMA = 1e4f;      // 1/SIGMA
    const float INV_GAMMA = 1e4f;      // 1/GAMMA
    const float EPSV      = 1e-10f;
    const float INV_RANGE = 1.0f / 99.0f;  // 1/(ZFAR-ZNEAR)
    const float ZFAR      = 100.0f;

    float zinv[KF];
    float prob[KF];
    int   face[KF];
    float zmax = EPSV;   // clip(max(z_inv), EPS) — start at EPS

    const int base = pix * KF;
#pragma unroll
    for (int k = 0; k < KF; k++) {
        int f = p2f[base + k];
        face[k] = f;
        float m = (f >= 0) ? 1.0f : 0.0f;
        float zi = (ZFAR - zbuf[base + k]) * INV_RANGE * m;
        zinv[k] = zi;
        zmax = fmaxf(zmax, zi);
        float dd = dists[base + k];
        // sigmoid(-d/sigma) = 1 / (1 + exp(d/sigma)); expf(inf)->inf -> 0, ok
        prob[k] = m / (1.0f + __expf(dd * INV_SIGMA));
    }

    float denom = 0.0f;
    float4 acc = make_float4(0.f, 0.f, 0.f, 0.f);
    const float* bpix = bary + (long)pix * (KF * 3);

#pragma unroll
    for (int k = 0; k < KF; k++) {
        float wk = prob[k] * __expf((zinv[k] - zmax) * INV_GAMMA);
        denom += wk;
        int f = (face[k] >= 0) ? face[k] : 0;
        const int* fv = faces + (long)f * 3;
        int v0 = fv[0], v1 = fv[1], v2 = fv[2];
        float b0 = bpix[k * 3 + 0];
        float b1 = bpix[k * 3 + 1];
        float b2 = bpix[k * 3 + 2];
        float4 f0 = vfeat[(long)v0 * 4 + cg];
        float4 f1 = vfeat[(long)v1 * 4 + cg];
        float4 f2 = vfeat[(long)v2 * 4 + cg];
        float tx = b0 * f0.x + b1 * f1.x + b2 * f2.x;
        float ty = b0 * f0.y + b1 * f1.y + b2 * f2.y;
        float tz = b0 * f0.z + b1 * f1.z + b2 * f2.z;
        float tw = b0 * f0.w + b1 * f1.w + b2 * f2.w;
        acc.x += wk * tx;
        acc.y += wk * ty;
        acc.z += wk * tz;
        acc.w += wk * tw;
    }

    float delta = fmaxf(__expf((EPSV - zmax) * INV_GAMMA), EPSV);
    denom += delta;
    float inv = 1.0f / denom;
    float4 b = bg4[cg];
    float4 o;
    o.x = (acc.x + delta * b.x) * inv;
    o.y = (acc.y + delta * b.y) * inv;
    o.z = (acc.z + delta * b.z) * inv;
    o.w = (acc.w + delta * b.w) * inv;
    out4[(long)pix * 4 + cg] = o;
}

extern "C" void kernel_launch(void* const* d_in, const int* in_sizes, int n_in,
                              void* d_out, int out_size)
{
    const float*  dists = (const float*)d_in[0];
    const float*  zbuf  = (const float*)d_in[1];
    const float*  bary  = (const float*)d_in[2];
    const float4* vfeat = (const float4*)d_in[3];
    const float4* bg4   = (const float4*)d_in[4];
    const int*    p2f   = (const int*)d_in[5];
    const int*    faces = (const int*)d_in[6];
    float4*       out4  = (float4*)d_out;

    int total = NPIX * 4;
    int block = 256;
    int grid  = (total + block - 1) / block;
    feature_shader_kernel<<<grid, block>>>(dists, zbuf, bary, vfeat, bg4, p2f, faces, out4);
}

// round 3
// speedup vs baseline: 1.5122x; 1.5122x over previous
#include <cuda_runtime.h>

// FeatureShader: softmax blend + barycentric vertex-feature sampling.
// N=4, H=256, W=256, K=8, C=16; V=100000, F=200000.
// Inputs: dists(N,H,W,K) f32 | zbuf f32 | bary(N,H,W,K,3) f32 |
//         verts_features(V,C) f32 | background(C) f32 | pix_to_face i32 | faces(F,3) i32
// Output: (N,H,W,C) f32

#define NPIX  (4 * 256 * 256)
#define KF    8
#define PPB   64          // pixels per block
#define TPB   256         // threads per block

__global__ __launch_bounds__(TPB)
void feature_shader_kernel(const float*  __restrict__ dists,
                           const float*  __restrict__ zbuf,
                           const float*  __restrict__ bary,
                           const float4* __restrict__ vfeat,   // (V, 4 x float4)
                           const float4* __restrict__ bg4,     // (4 x float4)
                           const int*    __restrict__ p2f,
                           const int*    __restrict__ faces,
                           float4*       __restrict__ out4)    // (NPIX, 4 x float4)
{
    // padded strides (9, 25) are coprime with 32 -> conflict-free smem
    __shared__ float s_z[PPB * 9];     // z_inv per (pix,k)
    __shared__ float s_w[PPB * 9];     // prob, then overwritten with wk
    __shared__ int   s_f[PPB * 9];     // face id per (pix,k)
    __shared__ float s_b[PPB * 25];    // bary (3 per k)
    __shared__ float s_inv[PPB];       // 1/denom
    __shared__ float s_dinv[PPB];      // delta/denom

    const float INV_SIGMA = 1e4f;
    const float INV_GAMMA = 1e4f;
    const float EPSV      = 1e-10f;
    const float INV_RANGE = 1.0f / 99.0f;   // 1/(ZFAR-ZNEAR)
    const float ZFARV     = 100.0f;

    const int  tid = threadIdx.x;
    const long pixBase = (long)blockIdx.x * PPB;

    // ---- Phase 1: coalesced streaming loads (each value loaded ONCE) ----
#pragma unroll
    for (int it = 0; it < 2; it++) {
        int  t    = tid + it * TPB;        // 0..511 = (pixL, k)
        int  pixL = t >> 3;
        int  k    = t & 7;
        long g    = pixBase * KF + t;

        int   f  = p2f[g];
        float m  = (f >= 0) ? 1.0f : 0.0f;
        float zi = (ZFARV - zbuf[g]) * INV_RANGE * m;
        float pr = m / (1.0f + __expf(dists[g] * INV_SIGMA));

        s_z[pixL * 9 + k] = zi;
        s_w[pixL * 9 + k] = pr;
        s_f[pixL * 9 + k] = (f >= 0) ? f : 0;

        const float* bp = bary + g * 3;
        s_b[pixL * 25 + k * 3 + 0] = bp[0];
        s_b[pixL * 25 + k * 3 + 1] = bp[1];
        s_b[pixL * 25 + k * 3 + 2] = bp[2];
    }
    __syncthreads();

    // ---- Phase 1b: per-pixel softmax reduction ----
    if (tid < PPB) {
        const int pix = tid;
        float zmax = EPSV;
#pragma unroll
        for (int k = 0; k < KF; k++)
            zmax = fmaxf(zmax, s_z[pix * 9 + k]);

        float delta = fmaxf(__expf((EPSV - zmax) * INV_GAMMA), EPSV);
        float denom = delta;
#pragma unroll
        for (int k = 0; k < KF; k++) {
            float wk = s_w[pix * 9 + k] * __expf((s_z[pix * 9 + k] - zmax) * INV_GAMMA);
            s_w[pix * 9 + k] = wk;
            denom += wk;
        }
        float inv = 1.0f / denom;
        s_inv[pix]  = inv;
        s_dinv[pix] = delta * inv;
    }
    __syncthreads();

    // ---- Phase 2: gather only surviving faces (wk != 0 is exact skip) ----
    const int pix = tid >> 2;     // local pixel
    const int cg  = tid & 3;      // channel group (4 floats)

    float4 acc = make_float4(0.f, 0.f, 0.f, 0.f);
#pragma unroll
    for (int k = 0; k < KF; k++) {
        float wk = s_w[pix * 9 + k];
        if (wk != 0.0f) {
            float b0 = wk * s_b[pix * 25 + k * 3 + 0];
            float b1 = wk * s_b[pix * 25 + k * 3 + 1];
            float b2 = wk * s_b[pix * 25 + k * 3 + 2];
            int fidx = s_f[pix * 9 + k];
            const int* fv = faces + (long)fidx * 3;
            int v0 = fv[0], v1 = fv[1], v2 = fv[2];
            float4 f0 = vfeat[(long)v0 * 4 + cg];
            float4 f1 = vfeat[(long)v1 * 4 + cg];
            float4 f2 = vfeat[(long)v2 * 4 + cg];
            acc.x += b0 * f0.x + b1 * f1.x + b2 * f2.x;
            acc.y += b0 * f0.y + b1 * f1.y + b2 * f2.y;
            acc.z += b0 * f0.z + b1 * f1.z + b2 * f2.z;
            acc.w += b0 * f0.w + b1 * f1.w + b2 * f2.w;
        }
    }

    float  inv  = s_inv[pix];
    float  dinv = s_dinv[pix];
    float4 b    = bg4[cg];
    float4 o;
    o.x = acc.x * inv + dinv * b.x;
    o.y = acc.y * inv + dinv * b.y;
    o.z = acc.z * inv + dinv * b.z;
    o.w = acc.w * inv + dinv * b.w;
    out4[(pixBase + pix) * 4 + cg] = o;
}

extern "C" void kernel_launch(void* const* d_in, const int* in_sizes, int n_in,
                              void* d_out, int out_size)
{
    const float*  dists = (const float*)d_in[0];
    const float*  zbuf  = (const float*)d_in[1];
    const float*  bary  = (const float*)d_in[2];
    const float4* vfeat = (const float4*)d_in[3];
    const float4* bg4   = (const float4*)d_in[4];
    const int*    p2f   = (const int*)d_in[5];
    const int*    faces = (const int*)d_in[6];
    float4*       out4  = (float4*)d_out;

    int grid = NPIX / PPB;   // 1024 blocks
    feature_shader_kernel<<<grid, TPB>>>(dists, zbuf, bary, vfeat, bg4, p2f, faces, out4);
}

// round 4
// speedup vs baseline: 1.6968x; 1.1221x over previous
#include <cuda_runtime.h>

// FeatureShader: softmax blend + barycentric vertex-feature sampling.
// N=4, H=256, W=256, K=8, C=16; V=100000, F=200000.
// Inputs: dists(N,H,W,K) f32 | zbuf f32 | bary(N,H,W,K,3) f32 |
//         verts_features(V,C) f32 | background(C) f32 | pix_to_face i32 | faces(F,3) i32
// Output: (N,H,W,C) f32

#define NPIX  (4 * 256 * 256)
#define KF    8
#define PPB   64          // pixels per block
#define TPB   512         // threads per block (= PPB * KF)

__global__ __launch_bounds__(TPB)
void feature_shader_kernel(const float*  __restrict__ dists,
                           const float*  __restrict__ zbuf,
                           const float*  __restrict__ bary,
                           const float2* __restrict__ vfeat2,  // (V, 8 x float2)
                           const float2* __restrict__ bg2,     // (8 x float2)
                           const int*    __restrict__ p2f,
                           const int*    __restrict__ faces,
                           float2*       __restrict__ out2)    // (NPIX, 8 x float2)
{
    // survivor records, padded stride 9 (float4/int2 base banks distinct per pixel)
    __shared__ float4 s_recA[PPB * 9];   // {wk*inv*b0, b1, b2, bitcast v0}
    __shared__ int2   s_recB[PPB * 9];   // {v1, v2}
    __shared__ int    s_cnt[PPB];
    __shared__ float  s_dinv[PPB];       // delta / denom

    const float INV_SIGMA = 1e4f;
    const float INV_GAMMA = 1e4f;
    const float EPSV      = 1e-10f;
    const float INV_RANGE = 1.0f / 99.0f;   // 1/(ZFAR-ZNEAR)
    const float ZFARV     = 100.0f;
    const float REL_THR   = 1e-7f;          // drop wk < REL_THR * wkmax (err << 1e-3)
    const unsigned FULL   = 0xffffffffu;

    const int  tid = threadIdx.x;
    const long pixBase = (long)blockIdx.x * PPB;

    // ================= Phase A: thread per (pixel, k) =================
    {
        const int  pixL = tid >> 3;        // local pixel 0..63
        const int  rel  = tid & 7;         // k
        const long g    = pixBase * KF + tid;

        int   f  = p2f[g];
        float m  = (f >= 0) ? 1.0f : 0.0f;
        float zi = (ZFARV - zbuf[g]) * INV_RANGE * m;
        float pr = m / (1.0f + __expf(dists[g] * INV_SIGMA));
        float b0 = bary[g * 3 + 0];
        float b1 = bary[g * 3 + 1];
        float b2 = bary[g * 3 + 2];

        // per-pixel max(z_inv) over the 8 lanes of this pixel group
        float zmax = zi;
        zmax = fmaxf(zmax, __shfl_xor_sync(FULL, zmax, 4));
        zmax = fmaxf(zmax, __shfl_xor_sync(FULL, zmax, 2));
        zmax = fmaxf(zmax, __shfl_xor_sync(FULL, zmax, 1));
        zmax = fmaxf(zmax, EPSV);          // clip(max, EPS)

        float wk = pr * __expf((zi - zmax) * INV_GAMMA);

        // denom = sum(wk) + delta   (all lanes of group get it)
        float dsum = wk;
        dsum += __shfl_xor_sync(FULL, dsum, 4);
        dsum += __shfl_xor_sync(FULL, dsum, 2);
        dsum += __shfl_xor_sync(FULL, dsum, 1);
        float delta = fmaxf(__expf((EPSV - zmax) * INV_GAMMA), EPSV);
        float inv   = 1.0f / (dsum + delta);

        // wkmax over group for the drop threshold
        float wkmax = wk;
        wkmax = fmaxf(wkmax, __shfl_xor_sync(FULL, wkmax, 4));
        wkmax = fmaxf(wkmax, __shfl_xor_sync(FULL, wkmax, 2));
        wkmax = fmaxf(wkmax, __shfl_xor_sync(FULL, wkmax, 1));

        bool keep = wk > wkmax * REL_THR;  // false for all if wkmax == 0

        unsigned bal  = __ballot_sync(FULL, keep);
        unsigned byte = (bal >> (tid & 24)) & 0xffu;
        int slot = __popc(byte & ((1u << rel) - 1u));
        int cnt  = __popc(byte);

        if (keep) {
            const int* fv = faces + (long)f * 3;
            int v0 = fv[0], v1 = fv[1], v2 = fv[2];
            float w = wk * inv;
            float4 rA;
            rA.x = w * b0;
            rA.y = w * b1;
            rA.z = w * b2;
            rA.w = __int_as_float(v0);
            s_recA[pixL * 9 + slot] = rA;
            s_recB[pixL * 9 + slot] = make_int2(v1, v2);
        }
        if (rel == 0) {
            s_cnt[pixL]  = cnt;
            s_dinv[pixL] = delta * inv;
        }
    }
    __syncthreads();

    // ============ Phase B: thread per (pixel, channel-pair) ============
    {
        const int pixL = tid >> 3;     // local pixel
        const int cgh  = tid & 7;      // channel pair (2 floats)

        const int   cnt  = s_cnt[pixL];
        const float dinv = s_dinv[pixL];

        float2 acc = make_float2(0.f, 0.f);
        for (int i = 0; i < cnt; i++) {
            float4 rA = s_recA[pixL * 9 + i];
            int2   rB = s_recB[pixL * 9 + i];
            int v0 = __float_as_int(rA.w);
            float2 f0 = vfeat2[(long)v0   * 8 + cgh];
            float2 f1 = vfeat2[(long)rB.x * 8 + cgh];
            float2 f2 = vfeat2[(long)rB.y * 8 + cgh];
            acc.x += rA.x * f0.x + rA.y * f1.x + rA.z * f2.x;
            acc.y += rA.x * f0.y + rA.y * f1.y + rA.z * f2.y;
        }

        float2 b = bg2[cgh];
        float2 o;
        o.x = acc.x + dinv * b.x;
        o.y = acc.y + dinv * b.y;
        out2[(pixBase + pixL) * 8 + cgh] = o;
    }
}

extern "C" void kernel_launch(void* const* d_in, const int* in_sizes, int n_in,
                              void* d_out, int out_size)
{
    const float*  dists = (const float*)d_in[0];
    const float*  zbuf  = (const float*)d_in[1];
    const float*  bary  = (const float*)d_in[2];
    const float2* vfeat = (const float2*)d_in[3];
    const float2* bg2   = (const float2*)d_in[4];
    const int*    p2f   = (const int*)d_in[5];
    const int*    faces = (const int*)d_in[6];
    float2*       out2  = (float2*)d_out;

    int grid = NPIX / PPB;   // 4096 blocks
    feature_shader_kernel<<<grid, TPB>>>(dists, zbuf, bary, vfeat, bg2, p2f, faces, out2);
}

// round 7
// speedup vs baseline: 1.7108x; 1.0082x over previous
#include <cuda_runtime.h>

// FeatureShader: softmax blend + barycentric vertex-feature sampling.
// N=4, H=256, W=256, K=8, C=16; V=100000, F=200000.
// Inputs: dists(N,H,W,K) f32 | zbuf f32 | bary(N,H,W,K,3) f32 |
//         verts_features(V,C) f32 | background(C) f32 | pix_to_face i32 | faces(F,3) i32
// Output: (N,H,W,C) f32
//
// Fully warp-local: each 8-lane group owns one pixel. Phase A computes the
// softmax weights + survivor records in registers; Phase B redistributes the
// records via shuffles (no smem, no __syncthreads) and gathers features only
// for surviving faces (wk below 1e-7 * denom contributes < 1e-6 rel err).

#define NPIX  (4 * 256 * 256)
#define KF    8
#define PPB   32          // pixels per block
#define TPB   256         // threads per block (= PPB * KF)

__global__ __launch_bounds__(TPB)
void feature_shader_kernel(const float*  __restrict__ dists,
                           const float*  __restrict__ zbuf,
                           const float*  __restrict__ bary,
                           const float2* __restrict__ vfeat2,  // (V, 8 x float2)
                           const float2* __restrict__ bg2,     // (8 x float2)
                           const int*    __restrict__ p2f,
                           const int*    __restrict__ faces,
                           float2*       __restrict__ out2)    // (NPIX, 8 x float2)
{
    const float INV_SIGMA = 1e4f;
    const float INV_GAMMA = 1e4f;
    const float EPSV      = 1e-10f;
    const float INV_RANGE = 1.0f / 99.0f;   // 1/(ZFAR-ZNEAR)
    const float ZFARV     = 100.0f;
    const float REL_THR   = 1e-7f;          // drop wk < REL_THR * denom
    const unsigned FULL   = 0xffffffffu;

    const int  tid  = threadIdx.x;
    const int  lane = tid & 31;
    const int  rel  = lane & 7;             // k within pixel / channel-pair in phase B
    const long g    = (long)blockIdx.x * (PPB * KF) + tid;   // (pix, k) flat index
    const long pix  = g >> 3;               // global pixel id of this group

    // ---------------- Phase A: per-(pixel,k) weight ----------------
    int   f  = p2f[g];
    float m  = (f >= 0) ? 1.0f : 0.0f;
    float zi = (ZFARV - zbuf[g]) * INV_RANGE * m;
    float pr = __fdividef(m, 1.0f + __expf(dists[g] * INV_SIGMA));
    float b0 = bary[g * 3 + 0];
    float b1 = bary[g * 3 + 1];
    float b2 = bary[g * 3 + 2];

    // max(z_inv) over the 8 lanes of this pixel group, clipped at EPS
    float zmax = zi;
    zmax = fmaxf(zmax, __shfl_xor_sync(FULL, zmax, 4));
    zmax = fmaxf(zmax, __shfl_xor_sync(FULL, zmax, 2));
    zmax = fmaxf(zmax, __shfl_xor_sync(FULL, zmax, 1));
    zmax = fmaxf(zmax, EPSV);

    float wk = pr * __expf((zi - zmax) * INV_GAMMA);

    // sum(wk) over group
    float dsum = wk;
    dsum += __shfl_xor_sync(FULL, dsum, 4);
    dsum += __shfl_xor_sync(FULL, dsum, 2);
    dsum += __shfl_xor_sync(FULL, dsum, 1);

    float delta = fmaxf(__expf((EPSV - zmax) * INV_GAMMA), EPSV);
    float inv   = __fdividef(1.0f, dsum + delta);
    float dinv  = delta * inv;

    bool keep = wk > dsum * REL_THR;     // dsum==0 -> keep false everywhere

    // survivor record (registers): premultiplied barys + vertex ids
    float w  = wk * inv;
    float r0 = w * b0, r1 = w * b1, r2 = w * b2;
    int v0 = 0, v1 = 0, v2 = 0;
    if (keep) {
        const int* fv = faces + (long)f * 3;
        v0 = fv[0]; v1 = fv[1]; v2 = fv[2];
    }

    unsigned bal  = __ballot_sync(FULL, keep);
    unsigned byte = (bal >> (lane & 24)) & 0xffu;
    int cnt = __popc(byte);

    // warp-uniform trip count = max survivors over the 4 groups in this warp
    int cntw = cnt;
    cntw = max(cntw, __shfl_xor_sync(FULL, cntw, 8));
    cntw = max(cntw, __shfl_xor_sync(FULL, cntw, 16));

    // ------------- Phase B: per-(pixel, channel-pair) gather -------------
    const int    cgh     = rel;              // channel pair 0..7
    const int    grpBase = lane & 24;
    const float2 b       = bg2[cgh];         // hoisted: overlaps gather latency
    float2 acc = make_float2(0.f, 0.f);

    for (int i = 0; i < cntw; i++) {
        unsigned srcRel = __fns(byte, 0, i + 1);   // i-th survivor lane (garbage if i>=cnt)
        unsigned src    = grpBase | (srcRel & 7);
        float w0 = __shfl_sync(FULL, r0, src);
        float w1 = __shfl_sync(FULL, r1, src);
        float w2 = __shfl_sync(FULL, r2, src);
        int   u0 = __shfl_sync(FULL, v0, src);
        int   u1 = __shfl_sync(FULL, v1, src);
        int   u2 = __shfl_sync(FULL, v2, src);
        if (i < cnt) {
            float2 f0 = vfeat2[(long)u0 * 8 + cgh];
            float2 f1 = vfeat2[(long)u1 * 8 + cgh];
            float2 f2 = vfeat2[(long)u2 * 8 + cgh];
            acc.x += w0 * f0.x + w1 * f1.x + w2 * f2.x;
            acc.y += w0 * f0.y + w1 * f1.y + w2 * f2.y;
        }
    }

    float2 o;
    o.x = acc.x + dinv * b.x;
    o.y = acc.y + dinv * b.y;
    out2[pix * 8 + cgh] = o;
}

extern "C" void kernel_launch(void* const* d_in, const int* in_sizes, int n_in,
                              void* d_out, int out_size)
{
    const float*  dists = (const float*)d_in[0];
    const float*  zbuf  = (const float*)d_in[1];
    const float*  bary  = (const float*)d_in[2];
    const float2* vfeat = (const float2*)d_in[3];
    const float2* bg2   = (const float2*)d_in[4];
    const int*    p2f   = (const int*)d_in[5];
    const int*    faces = (const int*)d_in[6];
    float2*       out2  = (float2*)d_out;

    int grid = NPIX / PPB;   // 8192 blocks
    feature_shader_kernel<<<grid, TPB>>>(dists, zbuf, bary, vfeat, bg2, p2f, faces, out2);
}